// round 15
// baseline (speedup 1.0000x reference)
#include <cuda_runtime.h>
#include <cuda_fp16.h>
#include <stdint.h>

#define BATCH 8
#define HW    4096
#define CDIM  384
#define KSEL  128

#define FEAT_N (BATCH * HW * CDIM)   // 12582912
#define MASK_N (BATCH * HW)          // 32768
#define BK_N   (BATCH * KSEL)        // 1024

#define KC       32
#define NCHUNK   (CDIM / KC)         // 12
#define TILE_HB  (128 * 40 * 2)      // 10240 B per 128x32 half tile (80B rows)
#define BUF_B    (2 * TILE_HB)       // a0,b0 per stage = 20480
#define SD2_STRH 136                 // smem d2 row stride (halfs), conflict-free
#define SROWCOL  40960
#define SMEM_P1  (SROWCOL + 1024)

#define EPS      0.015f
#define SENT     30000.0f
#define CAND_CAP (1 << 22)

// ---------------- scratch ----------------------------------------------------
__device__ __half g_h0a[FEAT_N], g_h0b[FEAT_N];    // fp16 leading parts
__device__ float  g_inv1[MASK_N], g_inv2[MASK_N];  // mask/norm per token
__device__ float  g_sq1[MASK_N], g_sq2[MASK_N];
__device__ unsigned g_rowmin[MASK_N], g_colmin[MASK_N];   // fp32 bits (>=0)
__device__ unsigned long long g_key1[MASK_N], g_key2[MASK_N];
__device__ __half g_d2[(size_t)HW * HW];           // 32 MB, reused per batch (L2-resident)
__device__ unsigned g_cand[CAND_CAP];
__device__ int g_ncand;

// ---------------- helpers ----------------------------------------------------
__device__ __forceinline__ uint32_t smem_u32(const void* p) {
    uint32_t a;
    asm("{ .reg .u64 t; cvta.to.shared.u64 t, %1; cvt.u32.u64 %0, t; }" : "=r"(a) : "l"(p));
    return a;
}
__device__ __forceinline__ void cp_async16(uint32_t dst, const void* src) {
    asm volatile("cp.async.cg.shared.global [%0], [%1], 16;" :: "r"(dst), "l"(src) : "memory");
}
__device__ __forceinline__ void ldsm4(uint32_t* r, uint32_t a) {
    asm volatile("ldmatrix.sync.aligned.m8n8.x4.shared.b16 {%0,%1,%2,%3}, [%4];"
                 : "=r"(r[0]), "=r"(r[1]), "=r"(r[2]), "=r"(r[3]) : "r"(a));
}
__device__ __forceinline__ void mma16816(float* c, const uint32_t* a, uint32_t b0, uint32_t b1) {
    asm volatile(
        "mma.sync.aligned.m16n8k16.row.col.f32.f16.f16.f32 "
        "{%0,%1,%2,%3}, {%4,%5,%6,%7}, {%8,%9}, {%0,%1,%2,%3};"
        : "+f"(c[0]), "+f"(c[1]), "+f"(c[2]), "+f"(c[3])
        : "r"(a[0]), "r"(a[1]), "r"(a[2]), "r"(a[3]), "r"(b0), "r"(b1));
}

// ------ normalize: fp16 h0 + inv + sq + init mins/keys/counter --------------
__global__ void normalize_kernel(const float* __restrict__ fa, const float* __restrict__ fb,
                                 const int* __restrict__ ma, const int* __restrict__ mb) {
    if (blockIdx.x == 0 && threadIdx.x == 0) g_ncand = 0;
    int half = gridDim.x >> 1;
    int which = blockIdx.x >= half;
    int blk   = which ? blockIdx.x - half : blockIdx.x;
    const float* f    = which ? fb : fa;
    const int*   mask = which ? mb : ma;

    int token = blk * 8 + (threadIdx.x >> 5);
    int lane  = threadIdx.x & 31;
    if (token >= MASK_N) return;
    const float* src = f + (size_t)token * CDIM;
    float v[12];
    float s = 0.f;
#pragma unroll
    for (int q = 0; q < 12; q++) { v[q] = src[lane + 32 * q]; s += v[q] * v[q]; }
#pragma unroll
    for (int o = 16; o; o >>= 1) s += __shfl_xor_sync(0xFFFFFFFFu, s, o);
    float m = (mask[token] > 0) ? 1.f : 0.f;
    float inv = m / sqrtf(s);
    __half* d0 = (which ? g_h0b : g_h0a) + (size_t)token * CDIM;
    float sq = 0.f;
#pragma unroll
    for (int q = 0; q < 12; q++) {
        float y = v[q] * inv;
        sq += y * y;
        d0[lane + 32 * q] = __float2half_rn(y);
    }
#pragma unroll
    for (int o = 16; o; o >>= 1) sq += __shfl_xor_sync(0xFFFFFFFFu, sq, o);
    if (lane == 0) {
        (which ? g_sq2 : g_sq1)[token] = sq;
        (which ? g_inv2 : g_inv1)[token] = inv;
        (which ? g_key2 : g_key1)[token] = ~0ULL;
        (which ? g_colmin : g_rowmin)[token] = 0x7F7FFFFFu;
        (which ? g_rowmin : g_colmin)[token] = 0x7F7FFFFFu;
    }
}

// ------------- pass 1 (per batch): GEMM + d2 store + row/col mins -----------
__global__ void __launch_bounds__(256)
mma_d2_kernel(const int* __restrict__ mask1, const int* __restrict__ mask2, int bt) {
    extern __shared__ char smem[];
    int it = blockIdx.y, jt = blockIdx.x;
    int tid = threadIdx.x, wid = tid >> 5, lane = tid & 31;
    int warp_m = wid >> 2, warp_n = wid & 3;

    uint32_t sbase = smem_u32(smem);
    unsigned* s_rmin = (unsigned*)(smem + SROWCOL);
    unsigned* s_cmin = (unsigned*)(smem + SROWCOL + 512);
    __half* s_d2 = (__half*)smem;
    if (tid < 128) { s_rmin[tid] = 0x7F7FFFFFu; s_cmin[tid] = 0x7F7FFFFFu; }

    size_t offA = ((size_t)bt * HW + it * 128) * CDIM;
    size_t offB = ((size_t)bt * HW + jt * 128) * CDIM;
    const __half* srcs[2] = { g_h0a + offA, g_h0b + offB };

    int ft = tid >> 7, fs0 = tid & 127;
    const __half* fsrc = srcs[ft];
    uint32_t fdst0 = sbase + ft * TILE_HB;

    float acc[4][4][4];
#pragma unroll
    for (int mf = 0; mf < 4; mf++)
#pragma unroll
        for (int nf = 0; nf < 4; nf++)
#pragma unroll
            for (int v = 0; v < 4; v++) acc[mf][nf][v] = 0.f;

#pragma unroll
    for (int r = 0; r < 4; r++) {
        int s = fs0 + r * 128, row = s >> 2, seg = s & 3;
        cp_async16(fdst0 + row * 80 + seg * 16, fsrc + (size_t)row * CDIM + seg * 8);
    }
    asm volatile("cp.async.commit_group;" ::: "memory");
    asm volatile("cp.async.wait_group 0;" ::: "memory");
    __syncthreads();

    int lrow = lane & 15, lsel = (lane >> 4) << 3;
    int kswap = warp_m;

    for (int c = 0; c < NCHUNK; c++) {
        uint32_t buf = (uint32_t)(c & 1) * BUF_B;
        if (c < NCHUNK - 1) {
            uint32_t nbuf = (uint32_t)((c + 1) & 1) * BUF_B;
            int k0g = (c + 1) * KC;
#pragma unroll
            for (int r = 0; r < 4; r++) {
                int s = fs0 + r * 128, row = s >> 2, seg = s & 3;
                cp_async16(fdst0 + nbuf + row * 80 + seg * 16,
                           fsrc + (size_t)row * CDIM + k0g + seg * 8);
            }
            asm volatile("cp.async.commit_group;" ::: "memory");
        }
        uint32_t aBase = sbase + buf + (uint32_t)(warp_m * 64 + lrow) * 80;
        uint32_t bBase = sbase + buf + TILE_HB + (uint32_t)(warp_n * 32 + lrow) * 80;
#pragma unroll
        for (int kk = 0; kk < 2; kk++) {
            uint32_t kb = (uint32_t)(((kk ^ kswap) ? 16 : 0) + lsel) * 2;
            uint32_t A0[4][4], B0[2][4];
#pragma unroll
            for (int mf = 0; mf < 4; mf++) ldsm4(A0[mf], aBase + kb + (uint32_t)(mf * 16) * 80);
#pragma unroll
            for (int ng = 0; ng < 2; ng++) ldsm4(B0[ng], bBase + kb + (uint32_t)(ng * 16) * 80);
#pragma unroll
            for (int mf = 0; mf < 4; mf++)
#pragma unroll
                for (int nf = 0; nf < 4; nf++)
                    mma16816(acc[mf][nf], A0[mf], B0[nf >> 1][nf & 1], B0[nf >> 1][(nf & 1) + 2]);
        }
        asm volatile("cp.async.wait_group 0;" ::: "memory");
        __syncthreads();
    }

    int   m1v[8], m2v[8];
    float sq1v[8], sq2v[8];
#pragma unroll
    for (int mf = 0; mf < 4; mf++)
#pragma unroll
        for (int h = 0; h < 2; h++) {
            int rl = warp_m * 64 + mf * 16 + (lane >> 2) + 8 * h;
            m1v[mf * 2 + h]  = mask1[bt * HW + it * 128 + rl];
            sq1v[mf * 2 + h] = g_sq1[bt * HW + it * 128 + rl];
        }
#pragma unroll
    for (int nf = 0; nf < 4; nf++)
#pragma unroll
        for (int h = 0; h < 2; h++) {
            int cl = warp_n * 32 + nf * 8 + (lane & 3) * 2 + h;
            m2v[nf * 2 + h]  = mask2[bt * HW + jt * 128 + cl];
            sq2v[nf * 2 + h] = g_sq2[bt * HW + jt * 128 + cl];
        }

    float rowbest[8], colbest[8];
#pragma unroll
    for (int q = 0; q < 8; q++) { rowbest[q] = 3.4e38f; colbest[q] = 3.4e38f; }

    float d2s[4][4][4];
#pragma unroll
    for (int mf = 0; mf < 4; mf++)
#pragma unroll
        for (int nf = 0; nf < 4; nf++)
#pragma unroll
            for (int v = 0; v < 4; v++) {
                int ri = mf * 2 + (v >> 1);
                int ci = nf * 2 + (v & 1);
                bool ok = (m1v[ri] > 0) && (m2v[ci] > 0);
                float d2 = ok ? fmaxf(sq1v[ri] + sq2v[ci] - 2.f * acc[mf][nf][v], 0.f) : SENT;
                d2s[mf][nf][v] = d2;
                rowbest[ri] = fminf(rowbest[ri], d2);
                colbest[ci] = fminf(colbest[ci], d2);
            }

#pragma unroll
    for (int mf = 0; mf < 4; mf++)
#pragma unroll
        for (int nf = 0; nf < 4; nf++)
#pragma unroll
            for (int h = 0; h < 2; h++) {
                int rl = warp_m * 64 + mf * 16 + (lane >> 2) + 8 * h;
                int cl0 = warp_n * 32 + nf * 8 + (lane & 3) * 2;
                __half2 pk = __floats2half2_rn(d2s[mf][nf][2 * h], d2s[mf][nf][2 * h + 1]);
                *(__half2*)(s_d2 + rl * SD2_STRH + cl0) = pk;
            }

#pragma unroll
    for (int q = 0; q < 8; q++) {
#pragma unroll
        for (int o = 1; o < 4; o <<= 1)
            rowbest[q] = fminf(rowbest[q], __shfl_xor_sync(0xFFFFFFFFu, rowbest[q], o));
        if ((lane & 3) == 0) {
            int rl = warp_m * 64 + (q >> 1) * 16 + (lane >> 2) + 8 * (q & 1);
            atomicMin(&s_rmin[rl], __float_as_uint(rowbest[q]));
        }
#pragma unroll
        for (int o = 4; o < 32; o <<= 1)
            colbest[q] = fminf(colbest[q], __shfl_xor_sync(0xFFFFFFFFu, colbest[q], o));
        if ((lane >> 2) == 0) {
            int cl = warp_n * 32 + (q >> 1) * 8 + (lane & 3) * 2 + (q & 1);
            atomicMin(&s_cmin[cl], __float_as_uint(colbest[q]));
        }
    }
    __syncthreads();

    __half* gout = g_d2 + (size_t)(it * 128) * HW + jt * 128;
#pragma unroll
    for (int q = 0; q < 8; q++) {
        int f = tid + q * 256;
        int r = f >> 4, c16 = f & 15;
        float4 val = *(const float4*)(s_d2 + r * SD2_STRH + c16 * 8);
        *(float4*)(gout + (size_t)r * HW + c16 * 8) = val;
    }
    if (tid < 128) {
        atomicMin(&g_rowmin[bt * HW + it * 128 + tid], s_rmin[tid]);
        atomicMin(&g_colmin[bt * HW + jt * 128 + tid], s_cmin[tid]);
    }
}

// ------------- pass 2 (per batch): scan d2 (L2-resident), emit candidates ---
__global__ void __launch_bounds__(128)
scan_kernel(int bt) {
    int i = blockIdx.x;
    int tid = threadIdx.x;
    float rm = __uint_as_float(g_rowmin[bt * HW + i]) + EPS;
    const __half* row = g_d2 + (size_t)i * HW;
    const unsigned* cmin = g_colmin + bt * HW;
#pragma unroll
    for (int q = 0; q < 4; q++) {
        int f = tid + q * 128;
        float4 raw = *(const float4*)(row + f * 8);
        const __half2* h2 = (const __half2*)&raw;
#pragma unroll
        for (int p = 0; p < 4; p++) {
            float2 d = __half22float2(h2[p]);
#pragma unroll
            for (int e = 0; e < 2; e++) {
                float d2v = e ? d.y : d.x;
                if (d2v < 20000.f) {
                    int j = f * 8 + p * 2 + e;
                    bool fr = d2v <= rm;
                    bool fc = d2v <= __uint_as_float(cmin[j]) + EPS;
                    if (fr || fc) {
                        unsigned w = (fr ? (1u << 27) : 0) | (fc ? (1u << 28) : 0) |
                                     ((unsigned)bt << 24) | ((unsigned)i << 12) | (unsigned)j;
                        int p0 = atomicAdd(&g_ncand, 1);
                        if (p0 < CAND_CAP) g_cand[p0] = w;
                    }
                }
            }
        }
    }
}

// ------------- pass 3: sentinel fixup + exact refine (raw features) ---------
__global__ void __launch_bounds__(256)
refine_kernel(const float* __restrict__ f1, const float* __restrict__ f2) {
    int tid = threadIdx.x, lane = tid & 31;
    int gw = blockIdx.x * 8 + (tid >> 5);
    int gt = blockIdx.x * 256 + tid;
    if (gt < MASK_N) {
        unsigned long long sk = ((unsigned long long)__float_as_uint(1.0e7f) << 32);
        if (__uint_as_float(g_rowmin[gt]) >= 20000.f) g_key1[gt] = sk;
        if (__uint_as_float(g_colmin[gt]) >= 20000.f) g_key2[gt] = sk;
    }
    int n = g_ncand; if (n > CAND_CAP) n = CAND_CAP;
    for (int c = gw; c < n; c += 16384) {
        unsigned w = g_cand[c];
        int j = w & 4095, i = (w >> 12) & 4095, bt = (w >> 24) & 7;
        float inv1 = g_inv1[bt * HW + i];
        float inv2 = g_inv2[bt * HW + j];
        const float* y1 = f1 + ((size_t)bt * HW + i) * CDIM;
        const float* y2 = f2 + ((size_t)bt * HW + j) * CDIM;
        float dot = 0.f;
#pragma unroll
        for (int q = 0; q < 3; q++) {
            int f = lane + 32 * q;
            float4 a = *(const float4*)(y1 + f * 4);
            float4 b = *(const float4*)(y2 + f * 4);
            float ax = a.x * inv1, ay = a.y * inv1, az = a.z * inv1, aw = a.w * inv1;
            float bx = b.x * inv2, by = b.y * inv2, bz = b.z * inv2, bw = b.w * inv2;
            dot += ax * bx + ay * by + az * bz + aw * bw;
        }
#pragma unroll
        for (int o = 16; o; o >>= 1) dot += __shfl_xor_sync(0xFFFFFFFFu, dot, o);
        if (lane == 0) {
            float d = sqrtf(fmaxf(g_sq1[bt * HW + i] + g_sq2[bt * HW + j] - 2.f * dot, 0.f));
            unsigned long long hb = ((unsigned long long)__float_as_uint(d) << 32);
            if (w & (1u << 27)) atomicMin(&g_key1[bt * HW + i], hb | (unsigned)j);
            if (w & (1u << 28)) atomicMin(&g_key2[bt * HW + j], hb | (unsigned)i);
        }
    }
}

// ------- cyclic diff + stable top-128 via counting selection ----------------
#define NBUCK 8192
__global__ void __launch_bounds__(512)
topk_kernel(const int* __restrict__ mask1, const int* __restrict__ mask2,
            const int* __restrict__ backup1, const int* __restrict__ backup2,
            float* __restrict__ out) {
    int b   = blockIdx.x >> 1;
    int dir = blockIdx.x & 1;
    const unsigned long long* keyF  = dir ? g_key2 : g_key1;
    const unsigned long long* keyBk = dir ? g_key1 : g_key2;
    const int* mSrc   = dir ? mask2   : mask1;
    const int* mDst   = dir ? mask1   : mask2;
    const int* backup = dir ? backup2 : backup1;

    __shared__ unsigned short s_d2[HW];
    __shared__ int s_hist[NBUCK];
    __shared__ int s_part[512];
    __shared__ unsigned long long s_list[KSEL];
    __shared__ int s_misc[4];

    int tid = threadIdx.x;
    if (tid < 4) s_misc[tid] = 0;
#pragma unroll
    for (int q = 0; q < NBUCK / 512; q++) s_hist[tid + q * 512] = 0;
    __syncthreads();

    int outBase = dir * (BATCH * KSEL * 2) + b * (KSEL * 2);

    int cnt = 0;
#pragma unroll
    for (int q = 0; q < HW / 512; q++) {
        int i = tid * (HW / 512) + q;
        int srcm = mSrc[b * HW + i];
        cnt += (srcm > 0);
        int mf = (int)(keyF[b * HW + i] & 0xFFFFFFFFull);
        unsigned d2;
        if (srcm > 0 && mDst[b * HW + mf] > 0) {
            int cyc = (int)(keyBk[b * HW + mf] & 0xFFFFFFFFull);
            int dx = (cyc >> 6) - (i >> 6);
            int dy = (cyc & 63) - (i & 63);
            d2 = (unsigned)(dx * dx + dy * dy);
        } else {
            d2 = NBUCK - 1;
        }
        s_d2[i] = (unsigned short)d2;
        atomicAdd(&s_hist[d2], 1);
    }
#pragma unroll
    for (int o = 16; o; o >>= 1) cnt += __shfl_xor_sync(0xFFFFFFFFu, cnt, o);
    if ((tid & 31) == 0) atomicAdd(&s_misc[0], cnt);
    __syncthreads();

    int hsum = 0;
#pragma unroll
    for (int q = 0; q < 16; q++) hsum += s_hist[tid * 16 + q];
    s_part[tid] = hsum;
    __syncthreads();
    for (int off = 1; off < 512; off <<= 1) {
        int v = (tid >= off) ? s_part[tid - off] : 0;
        __syncthreads();
        s_part[tid] += v;
        __syncthreads();
    }
    int hbase = s_part[tid] - hsum;
    if (hbase < KSEL && hbase + hsum >= KSEL) {
        int c = hbase;
#pragma unroll
        for (int q = 0; q < 16; q++) {
            int h = s_hist[tid * 16 + q];
            if (c + h >= KSEL) { s_misc[1] = tid * 16 + q; s_misc[2] = c; break; }
            c += h;
        }
    }
    __syncthreads();

    bool useTop = (s_misc[0] >= KSEL);
    if (useTop) {
        int T = s_misc[1], n1 = s_misc[2];
        for (int q = 0; q < HW / 512; q++) {
            int i = tid * (HW / 512) + q;
            if (s_d2[i] < T) {
                int p = atomicAdd(&s_misc[3], 1);
                s_list[p] = ((unsigned long long)s_d2[i] << 32) | (unsigned)i;
            }
        }
        __syncthreads();
        if (tid >= n1 && tid < KSEL) s_list[tid] = ~0ULL;
        __syncthreads();
        for (int k = 2; k <= KSEL; k <<= 1)
            for (int j = k >> 1; j > 0; j >>= 1) {
                if (tid < KSEL) {
                    int ixj = tid ^ j;
                    if (ixj > tid) {
                        unsigned long long a = s_list[tid], c2 = s_list[ixj];
                        bool up = ((tid & k) == 0);
                        if ((a > c2) == up) { s_list[tid] = c2; s_list[ixj] = a; }
                    }
                }
                __syncthreads();
            }
        if (tid < n1) {
            int idx = (int)(s_list[tid] & 0xFFFFFFFFull);
            int match = (int)(keyF[b * HW + idx] & 0xFFFFFFFFull);
            out[outBase + tid * 2]     = (float)idx;
            out[outBase + tid * 2 + 1] = (float)match;
        }
        int myf[HW / 512], fsum = 0;
#pragma unroll
        for (int q = 0; q < HW / 512; q++) {
            int i = tid * (HW / 512) + q;
            myf[q] = (s_d2[i] == T);
            fsum += myf[q];
        }
        __syncthreads();
        s_part[tid] = fsum;
        __syncthreads();
        for (int off = 1; off < 512; off <<= 1) {
            int v = (tid >= off) ? s_part[tid - off] : 0;
            __syncthreads();
            s_part[tid] += v;
            __syncthreads();
        }
        int p = s_part[tid] - fsum;
        int need = KSEL - n1;
#pragma unroll
        for (int q = 0; q < HW / 512; q++) {
            if (myf[q]) {
                if (p < need) {
                    int i = tid * (HW / 512) + q;
                    int match = (int)(keyF[b * HW + i] & 0xFFFFFFFFull);
                    out[outBase + (n1 + p) * 2]     = (float)i;
                    out[outBase + (n1 + p) * 2 + 1] = (float)match;
                }
                p++;
            }
        }
    } else {
        if (tid < KSEL) {
            int idx = backup[b * KSEL + tid];
            int match = (int)(keyF[b * HW + idx] & 0xFFFFFFFFull);
            out[outBase + tid * 2]     = (float)idx;
            out[outBase + tid * 2 + 1] = (float)match;
        }
    }
}

// ---------------- launch ----------------------------------------------------
extern "C" void kernel_launch(void* const* d_in, const int* in_sizes, int n_in,
                              void* d_out, int out_size) {
    const float* f1 = nullptr; const float* f2 = nullptr;
    const int* mask1 = nullptr; const int* mask2 = nullptr;
    const int* bk1 = nullptr; const int* bk2 = nullptr;
    for (int i = 0; i < n_in; i++) {
        long long sz = in_sizes[i];
        if (sz == FEAT_N || sz == (long long)FEAT_N * 4) {
            if (!f1) f1 = (const float*)d_in[i]; else f2 = (const float*)d_in[i];
        } else if (sz == MASK_N || sz == (long long)MASK_N * 4) {
            if (!mask1) mask1 = (const int*)d_in[i]; else mask2 = (const int*)d_in[i];
        } else if (sz == BK_N || sz == (long long)BK_N * 4) {
            if (!bk1) bk1 = (const int*)d_in[i]; else bk2 = (const int*)d_in[i];
        }
    }
    if (!f1 || !f2 || !mask1 || !mask2 || !bk1 || !bk2) {
        f1    = (const float*)d_in[0];
        f2    = (const float*)d_in[1];
        mask1 = (const int*)d_in[2];
        mask2 = (const int*)d_in[3];
        bk1   = (const int*)d_in[4];
        bk2   = (const int*)d_in[5];
    }
    float* out = (float*)d_out;

    cudaFuncSetAttribute(mma_d2_kernel,
                         cudaFuncAttributeMaxDynamicSharedMemorySize, SMEM_P1);

    normalize_kernel<<<2 * (MASK_N / 8), 256>>>(f1, f2, mask1, mask2);
    for (int bt = 0; bt < BATCH; bt++) {
        dim3 grid(HW / 128, HW / 128);
        mma_d2_kernel<<<grid, 256, SMEM_P1>>>(mask1, mask2, bt);
        scan_kernel<<<HW, 128>>>(bt);
    }
    refine_kernel<<<2048, 256>>>(f1, f2);
    topk_kernel<<<BATCH * 2, 512>>>(mask1, mask2, bk1, bk2, out);
}

// round 16
// speedup vs baseline: 1.1755x; 1.1755x over previous
#include <cuda_runtime.h>
#include <cuda_fp16.h>
#include <stdint.h>

#define BATCH 8
#define HW    4096
#define CDIM  384
#define KSEL  128

#define FEAT_N (BATCH * HW * CDIM)
#define MASK_N (BATCH * HW)
#define BK_N   (BATCH * KSEL)

#define KC       32
#define NCHUNK   (CDIM / KC)         // 12
#define TILE_HB  (128 * 40 * 2)      // 10240 B per 128x32 half tile (80B rows)
#define BUF_B    (2 * TILE_HB)       // 20480 per stage
#define SMEM_TRI 40960               // triples after 2 bufs
#define SMEM_P1  (SMEM_TRI + 4096 + 2048 + 2048 + 1024)   // 50176

#define EPS      0.015f
#define SENT     30000.0f
#define CAND_CAP (1 << 23)

// ---------------- scratch ----------------------------------------------------
__device__ __half g_h0a[FEAT_N], g_h0b[FEAT_N];
__device__ float  g_inv1[MASK_N], g_inv2[MASK_N];
__device__ float  g_sq1[MASK_N], g_sq2[MASK_N];
__device__ unsigned g_rowmin[MASK_N], g_colmin[MASK_N];
__device__ unsigned long long g_key1[MASK_N], g_key2[MASK_N];
// per-tile summaries: [(bt*32 + tile)*HW + line] -> (half m1)<<48 | (half m2)<<32 | argIdx
__device__ unsigned long long g_rowinfo[(size_t)MASK_N * 32];
__device__ unsigned long long g_colinfo[(size_t)MASK_N * 32];
__device__ unsigned g_cand[CAND_CAP];
__device__ int g_ncand;

// ---------------- helpers ----------------------------------------------------
__device__ __forceinline__ uint32_t smem_u32(const void* p) {
    uint32_t a;
    asm("{ .reg .u64 t; cvta.to.shared.u64 t, %1; cvt.u32.u64 %0, t; }" : "=r"(a) : "l"(p));
    return a;
}
__device__ __forceinline__ void cp_async16(uint32_t dst, const void* src) {
    asm volatile("cp.async.cg.shared.global [%0], [%1], 16;" :: "r"(dst), "l"(src) : "memory");
}
__device__ __forceinline__ void ldsm4(uint32_t* r, uint32_t a) {
    asm volatile("ldmatrix.sync.aligned.m8n8.x4.shared.b16 {%0,%1,%2,%3}, [%4];"
                 : "=r"(r[0]), "=r"(r[1]), "=r"(r[2]), "=r"(r[3]) : "r"(a));
}
__device__ __forceinline__ void mma16816(float* c, const uint32_t* a, uint32_t b0, uint32_t b1) {
    asm volatile(
        "mma.sync.aligned.m16n8k16.row.col.f32.f16.f16.f32 "
        "{%0,%1,%2,%3}, {%4,%5,%6,%7}, {%8,%9}, {%0,%1,%2,%3};"
        : "+f"(c[0]), "+f"(c[1]), "+f"(c[2]), "+f"(c[3])
        : "r"(a[0]), "r"(a[1]), "r"(a[2]), "r"(a[3]), "r"(b0), "r"(b1));
}
// merge triple (m1,j,m2) with (m1o,jo,m2o)
__device__ __forceinline__ void tri_merge(float& m1, int& j, float& m2,
                                          float m1o, int jo, float m2o) {
    float mx = fmaxf(m1, m1o);
    float mn = fminf(m2, m2o);
    if (m1o < m1) { m1 = m1o; j = jo; }
    m2 = fminf(mx, mn);
}

// ------ normalize: fp16 h0 + inv + sq + key init ----------------------------
__global__ void normalize_kernel(const float* __restrict__ fa, const float* __restrict__ fb,
                                 const int* __restrict__ ma, const int* __restrict__ mb) {
    if (blockIdx.x == 0 && threadIdx.x == 0) g_ncand = 0;
    int half = gridDim.x >> 1;
    int which = blockIdx.x >= half;
    int blk   = which ? blockIdx.x - half : blockIdx.x;
    const float* f    = which ? fb : fa;
    const int*   mask = which ? mb : ma;

    int token = blk * 8 + (threadIdx.x >> 5);
    int lane  = threadIdx.x & 31;
    if (token >= MASK_N) return;
    const float* src = f + (size_t)token * CDIM;
    float v[12];
    float s = 0.f;
#pragma unroll
    for (int q = 0; q < 12; q++) { v[q] = src[lane + 32 * q]; s += v[q] * v[q]; }
#pragma unroll
    for (int o = 16; o; o >>= 1) s += __shfl_xor_sync(0xFFFFFFFFu, s, o);
    float m = (mask[token] > 0) ? 1.f : 0.f;
    float inv = m / sqrtf(s);
    __half* d0 = (which ? g_h0b : g_h0a) + (size_t)token * CDIM;
    float sq = 0.f;
#pragma unroll
    for (int q = 0; q < 12; q++) {
        float y = v[q] * inv;
        sq += y * y;
        d0[lane + 32 * q] = __float2half_rn(y);
    }
#pragma unroll
    for (int o = 16; o; o >>= 1) sq += __shfl_xor_sync(0xFFFFFFFFu, sq, o);
    if (lane == 0) {
        (which ? g_sq2 : g_sq1)[token] = sq;
        (which ? g_inv2 : g_inv1)[token] = inv;
        (which ? g_key2 : g_key1)[token] = ~0ULL;
    }
}

// ------------- pass 1: GEMM + per-tile (min1,min2,argmin) summaries ---------
__global__ void __launch_bounds__(256, 2)
mma_min_kernel(const int* __restrict__ mask1, const int* __restrict__ mask2) {
    extern __shared__ char smem[];
    int bt = blockIdx.z, it = blockIdx.y, jt = blockIdx.x;
    int tid = threadIdx.x, wid = tid >> 5, lane = tid & 31;
    int warp_m = wid >> 2, warp_n = wid & 3;

    uint32_t sbase = smem_u32(smem);
    unsigned long long* s_r1 = (unsigned long long*)(smem + SMEM_TRI);          // 128*4
    unsigned* s_r2 = (unsigned*)(smem + SMEM_TRI + 4096);                       // 128*4
    unsigned long long* s_c1 = (unsigned long long*)(smem + SMEM_TRI + 6144);   // 128*2
    unsigned* s_c2 = (unsigned*)(smem + SMEM_TRI + 8192);                       // 128*2

    size_t offA = ((size_t)bt * HW + it * 128) * CDIM;
    size_t offB = ((size_t)bt * HW + jt * 128) * CDIM;
    const __half* srcs[2] = { g_h0a + offA, g_h0b + offB };

    int ft = tid >> 7, fs0 = tid & 127;
    const __half* fsrc = srcs[ft];
    uint32_t fdst0 = sbase + ft * TILE_HB;

    float acc[4][4][4];
#pragma unroll
    for (int mf = 0; mf < 4; mf++)
#pragma unroll
        for (int nf = 0; nf < 4; nf++)
#pragma unroll
            for (int v = 0; v < 4; v++) acc[mf][nf][v] = 0.f;

#pragma unroll
    for (int r = 0; r < 4; r++) {
        int s = fs0 + r * 128, row = s >> 2, seg = s & 3;
        cp_async16(fdst0 + row * 80 + seg * 16, fsrc + (size_t)row * CDIM + seg * 8);
    }
    asm volatile("cp.async.commit_group;" ::: "memory");
    asm volatile("cp.async.wait_group 0;" ::: "memory");
    __syncthreads();

    int lrow = lane & 15, lsel = (lane >> 4) << 3;
    int kswap = warp_m;

    for (int c = 0; c < NCHUNK; c++) {
        uint32_t buf = (uint32_t)(c & 1) * BUF_B;
        if (c < NCHUNK - 1) {
            uint32_t nbuf = (uint32_t)((c + 1) & 1) * BUF_B;
            int k0g = (c + 1) * KC;
#pragma unroll
            for (int r = 0; r < 4; r++) {
                int s = fs0 + r * 128, row = s >> 2, seg = s & 3;
                cp_async16(fdst0 + nbuf + row * 80 + seg * 16,
                           fsrc + (size_t)row * CDIM + k0g + seg * 8);
            }
            asm volatile("cp.async.commit_group;" ::: "memory");
        }
        uint32_t aBase = sbase + buf + (uint32_t)(warp_m * 64 + lrow) * 80;
        uint32_t bBase = sbase + buf + TILE_HB + (uint32_t)(warp_n * 32 + lrow) * 80;
#pragma unroll
        for (int kk = 0; kk < 2; kk++) {
            uint32_t kb = (uint32_t)(((kk ^ kswap) ? 16 : 0) + lsel) * 2;
            uint32_t A0[4][4], B0[2][4];
#pragma unroll
            for (int mf = 0; mf < 4; mf++) ldsm4(A0[mf], aBase + kb + (uint32_t)(mf * 16) * 80);
#pragma unroll
            for (int ng = 0; ng < 2; ng++) ldsm4(B0[ng], bBase + kb + (uint32_t)(ng * 16) * 80);
#pragma unroll
            for (int mf = 0; mf < 4; mf++)
#pragma unroll
                for (int nf = 0; nf < 4; nf++)
                    mma16816(acc[mf][nf], A0[mf], B0[nf >> 1][nf & 1], B0[nf >> 1][(nf & 1) + 2]);
        }
        asm volatile("cp.async.wait_group 0;" ::: "memory");
        __syncthreads();
    }

    // ---- epilogue: masks/sq ----
    int   m1v[8], m2v[8];
    float sq1v[8], sq2v[8];
#pragma unroll
    for (int mf = 0; mf < 4; mf++)
#pragma unroll
        for (int h = 0; h < 2; h++) {
            int rl = warp_m * 64 + mf * 16 + (lane >> 2) + 8 * h;
            m1v[mf * 2 + h]  = mask1[bt * HW + it * 128 + rl];
            sq1v[mf * 2 + h] = g_sq1[bt * HW + it * 128 + rl];
        }
#pragma unroll
    for (int nf = 0; nf < 4; nf++)
#pragma unroll
        for (int h = 0; h < 2; h++) {
            int cl = warp_n * 32 + nf * 8 + (lane & 3) * 2 + h;
            m2v[nf * 2 + h]  = mask2[bt * HW + jt * 128 + cl];
            sq2v[nf * 2 + h] = g_sq2[bt * HW + jt * 128 + cl];
        }

    // ---- pass A: row triples ----
    {
        float r1[8], r2[8]; int rj[8];
#pragma unroll
        for (int q = 0; q < 8; q++) { r1[q] = 3.4e38f; r2[q] = 3.4e38f; rj[q] = 0; }
#pragma unroll
        for (int mf = 0; mf < 4; mf++)
#pragma unroll
            for (int nf = 0; nf < 4; nf++)
#pragma unroll
                for (int v = 0; v < 4; v++) {
                    int ri = mf * 2 + (v >> 1);
                    int ci = nf * 2 + (v & 1);
                    int clg = jt * 128 + warp_n * 32 + nf * 8 + (lane & 3) * 2 + (v & 1);
                    bool ok = (m1v[ri] > 0) && (m2v[ci] > 0);
                    float d2 = ok ? fmaxf(sq1v[ri] + sq2v[ci] - 2.f * acc[mf][nf][v], 0.f) : SENT;
                    if (d2 < r1[ri]) { r2[ri] = r1[ri]; r1[ri] = d2; rj[ri] = clg; }
                    else r2[ri] = fminf(r2[ri], d2);
                }
#pragma unroll
        for (int q = 0; q < 8; q++) {
#pragma unroll
            for (int o = 1; o < 4; o <<= 1) {
                float m1o = __shfl_xor_sync(0xFFFFFFFFu, r1[q], o);
                int   jo  = __shfl_xor_sync(0xFFFFFFFFu, rj[q], o);
                float m2o = __shfl_xor_sync(0xFFFFFFFFu, r2[q], o);
                tri_merge(r1[q], rj[q], r2[q], m1o, jo, m2o);
            }
            if ((lane & 3) == 0) {
                int rl = warp_m * 64 + (q >> 1) * 16 + (lane >> 2) + 8 * (q & 1);
                s_r1[rl * 4 + warp_n] =
                    ((unsigned long long)__float_as_uint(r1[q]) << 32) | (unsigned)rj[q];
                s_r2[rl * 4 + warp_n] = __float_as_uint(r2[q]);
            }
        }
    }
    // ---- pass B: col triples ----
    {
        float c1[8], c2[8]; int cj[8];
#pragma unroll
        for (int q = 0; q < 8; q++) { c1[q] = 3.4e38f; c2[q] = 3.4e38f; cj[q] = 0; }
#pragma unroll
        for (int mf = 0; mf < 4; mf++)
#pragma unroll
            for (int nf = 0; nf < 4; nf++)
#pragma unroll
                for (int v = 0; v < 4; v++) {
                    int ri = mf * 2 + (v >> 1);
                    int ci = nf * 2 + (v & 1);
                    int rlg = it * 128 + warp_m * 64 + mf * 16 + (lane >> 2) + 8 * (v >> 1);
                    bool ok = (m1v[ri] > 0) && (m2v[ci] > 0);
                    float d2 = ok ? fmaxf(sq1v[ri] + sq2v[ci] - 2.f * acc[mf][nf][v], 0.f) : SENT;
                    if (d2 < c1[ci]) { c2[ci] = c1[ci]; c1[ci] = d2; cj[ci] = rlg; }
                    else c2[ci] = fminf(c2[ci], d2);
                }
#pragma unroll
        for (int q = 0; q < 8; q++) {
#pragma unroll
            for (int o = 4; o < 32; o <<= 1) {
                float m1o = __shfl_xor_sync(0xFFFFFFFFu, c1[q], o);
                int   jo  = __shfl_xor_sync(0xFFFFFFFFu, cj[q], o);
                float m2o = __shfl_xor_sync(0xFFFFFFFFu, c2[q], o);
                tri_merge(c1[q], cj[q], c2[q], m1o, jo, m2o);
            }
            if (lane < 4) {
                int cl = warp_n * 32 + (q >> 1) * 8 + (lane & 3) * 2 + (q & 1);
                s_c1[cl * 2 + warp_m] =
                    ((unsigned long long)__float_as_uint(c1[q]) << 32) | (unsigned)cj[q];
                s_c2[cl * 2 + warp_m] = __float_as_uint(c2[q]);
            }
        }
    }
    __syncthreads();

    if (tid < 128) {
        // rows: combine 4 partials
        float m1 = 3.4e38f, m2 = 3.4e38f; int j = 0;
#pragma unroll
        for (int w = 0; w < 4; w++) {
            unsigned long long p = s_r1[tid * 4 + w];
            tri_merge(m1, j, m2, __uint_as_float((unsigned)(p >> 32)), (int)(unsigned)p,
                      __uint_as_float(s_r2[tid * 4 + w]));
        }
        unsigned long long pk =
            ((unsigned long long)__half_as_ushort(__float2half_rn(m1)) << 48) |
            ((unsigned long long)__half_as_ushort(__float2half_rn(m2)) << 32) | (unsigned)j;
        g_rowinfo[((size_t)(bt * 32 + jt)) * HW + it * 128 + tid] = pk;

        // cols: combine 2 partials
        m1 = 3.4e38f; m2 = 3.4e38f; j = 0;
#pragma unroll
        for (int w = 0; w < 2; w++) {
            unsigned long long p = s_c1[tid * 2 + w];
            tri_merge(m1, j, m2, __uint_as_float((unsigned)(p >> 32)), (int)(unsigned)p,
                      __uint_as_float(s_c2[tid * 2 + w]));
        }
        pk = ((unsigned long long)__half_as_ushort(__float2half_rn(m1)) << 48) |
             ((unsigned long long)__half_as_ushort(__float2half_rn(m2)) << 32) | (unsigned)j;
        g_colinfo[((size_t)(bt * 32 + it)) * HW + jt * 128 + tid] = pk;
    }
}

// ------------- pass 2: scan summaries, emit candidates + global mins --------
__global__ void __launch_bounds__(256)
scan_kernel() {
    int wid = threadIdx.x >> 5, lane = threadIdx.x & 31;
    int wg = blockIdx.x * 8 + wid;                 // 0 .. 2*MASK_N-1
    int dir = wg >= MASK_N;
    int idx = wg - (dir ? MASK_N : 0);
    int bt = idx >> 12, i = idx & 4095;
    const unsigned long long* info = dir ? g_colinfo : g_rowinfo;
    unsigned long long p = info[((size_t)(bt * 32 + lane)) * HW + i];
    float m1 = __half2float(__ushort_as_half((unsigned short)(p >> 48)));
    float m2 = __half2float(__ushort_as_half((unsigned short)(p >> 32)));
    unsigned am = (unsigned)p;                     // partner index
    float rm = m1;
#pragma unroll
    for (int o = 16; o; o >>= 1) rm = fminf(rm, __shfl_xor_sync(0xFFFFFFFFu, rm, o));
    if (lane == 0) (dir ? g_colmin : g_rowmin)[bt * HW + i] = __float_as_uint(rm);
    if (rm >= 20000.f) return;
    float thr = rm + EPS;
    unsigned flag = dir ? (1u << 28) : (1u << 27);
    unsigned bthi = (unsigned)bt << 24;

    bool e1 = (m1 <= thr);
    unsigned bal = __ballot_sync(0xFFFFFFFFu, e1);
    int nb = __popc(bal);
    int base = 0;
    if (lane == 0 && nb) base = atomicAdd(&g_ncand, nb);
    base = __shfl_sync(0xFFFFFFFFu, base, 0);
    if (e1) {
        int off = __popc(bal & ((1u << lane) - 1));
        unsigned w = flag | bthi |
                     (dir ? ((am << 12) | (unsigned)i) : (((unsigned)i << 12) | am));
        if (base + off < CAND_CAP) g_cand[base + off] = w;
    }
    if (m2 <= thr) {                               // flood this tile (rare)
        int b2 = atomicAdd(&g_ncand, 128);
        for (int t = 0; t < 128; t++) {
            unsigned oth = (unsigned)(lane * 128 + t);
            unsigned w = flag | bthi |
                         (dir ? ((oth << 12) | (unsigned)i) : (((unsigned)i << 12) | oth));
            if (b2 + t < CAND_CAP) g_cand[b2 + t] = w;
        }
    }
}

// ------------- pass 3: sentinel fixup + exact refine ------------------------
__global__ void __launch_bounds__(256)
refine_kernel(const float* __restrict__ f1, const float* __restrict__ f2) {
    int tid = threadIdx.x, lane = tid & 31;
    int gw = blockIdx.x * 8 + (tid >> 5);
    int gt = blockIdx.x * 256 + tid;
    if (gt < MASK_N) {
        unsigned long long sk = ((unsigned long long)__float_as_uint(1.0e7f) << 32);
        if (__uint_as_float(g_rowmin[gt]) >= 20000.f) g_key1[gt] = sk;
        if (__uint_as_float(g_colmin[gt]) >= 20000.f) g_key2[gt] = sk;
    }
    int n = g_ncand; if (n > CAND_CAP) n = CAND_CAP;
    for (int c = gw; c < n; c += 16384) {
        unsigned w = g_cand[c];
        int j = w & 4095, i = (w >> 12) & 4095, bt = (w >> 24) & 7;
        float inv1 = g_inv1[bt * HW + i];
        float inv2 = g_inv2[bt * HW + j];
        if (inv1 == 0.f || inv2 == 0.f) continue;   // masked (flood artifacts)
        const float* y1 = f1 + ((size_t)bt * HW + i) * CDIM;
        const float* y2 = f2 + ((size_t)bt * HW + j) * CDIM;
        float dot = 0.f;
#pragma unroll
        for (int q = 0; q < 3; q++) {
            int f = lane + 32 * q;
            float4 a = *(const float4*)(y1 + f * 4);
            float4 b = *(const float4*)(y2 + f * 4);
            float ax = a.x * inv1, ay = a.y * inv1, az = a.z * inv1, aw = a.w * inv1;
            float bx = b.x * inv2, by = b.y * inv2, bz = b.z * inv2, bw = b.w * inv2;
            dot += ax * bx + ay * by + az * bz + aw * bw;
        }
#pragma unroll
        for (int o = 16; o; o >>= 1) dot += __shfl_xor_sync(0xFFFFFFFFu, dot, o);
        if (lane == 0) {
            float d = sqrtf(fmaxf(g_sq1[bt * HW + i] + g_sq2[bt * HW + j] - 2.f * dot, 0.f));
            unsigned long long hb = ((unsigned long long)__float_as_uint(d) << 32);
            if (w & (1u << 27)) atomicMin(&g_key1[bt * HW + i], hb | (unsigned)j);
            if (w & (1u << 28)) atomicMin(&g_key2[bt * HW + j], hb | (unsigned)i);
        }
    }
}

// ------- cyclic diff + stable top-128 via counting selection ----------------
#define NBUCK 8192
__global__ void __launch_bounds__(512)
topk_kernel(const int* __restrict__ mask1, const int* __restrict__ mask2,
            const int* __restrict__ backup1, const int* __restrict__ backup2,
            float* __restrict__ out) {
    int b   = blockIdx.x >> 1;
    int dir = blockIdx.x & 1;
    const unsigned long long* keyF  = dir ? g_key2 : g_key1;
    const unsigned long long* keyBk = dir ? g_key1 : g_key2;
    const int* mSrc   = dir ? mask2   : mask1;
    const int* mDst   = dir ? mask1   : mask2;
    const int* backup = dir ? backup2 : backup1;

    __shared__ unsigned short s_d2[HW];
    __shared__ int s_hist[NBUCK];
    __shared__ int s_part[512];
    __shared__ unsigned long long s_list[KSEL];
    __shared__ int s_misc[4];

    int tid = threadIdx.x;
    if (tid < 4) s_misc[tid] = 0;
#pragma unroll
    for (int q = 0; q < NBUCK / 512; q++) s_hist[tid + q * 512] = 0;
    __syncthreads();

    int outBase = dir * (BATCH * KSEL * 2) + b * (KSEL * 2);

    int cnt = 0;
#pragma unroll
    for (int q = 0; q < HW / 512; q++) {
        int i = tid * (HW / 512) + q;
        int srcm = mSrc[b * HW + i];
        cnt += (srcm > 0);
        int mf = (int)(keyF[b * HW + i] & 0xFFFFFFFFull);
        unsigned d2;
        if (srcm > 0 && mDst[b * HW + mf] > 0) {
            int cyc = (int)(keyBk[b * HW + mf] & 0xFFFFFFFFull);
            int dx = (cyc >> 6) - (i >> 6);
            int dy = (cyc & 63) - (i & 63);
            d2 = (unsigned)(dx * dx + dy * dy);
        } else {
            d2 = NBUCK - 1;
        }
        s_d2[i] = (unsigned short)d2;
        atomicAdd(&s_hist[d2], 1);
    }
#pragma unroll
    for (int o = 16; o; o >>= 1) cnt += __shfl_xor_sync(0xFFFFFFFFu, cnt, o);
    if ((tid & 31) == 0) atomicAdd(&s_misc[0], cnt);
    __syncthreads();

    int hsum = 0;
#pragma unroll
    for (int q = 0; q < 16; q++) hsum += s_hist[tid * 16 + q];
    s_part[tid] = hsum;
    __syncthreads();
    for (int off = 1; off < 512; off <<= 1) {
        int v = (tid >= off) ? s_part[tid - off] : 0;
        __syncthreads();
        s_part[tid] += v;
        __syncthreads();
    }
    int hbase = s_part[tid] - hsum;
    if (hbase < KSEL && hbase + hsum >= KSEL) {
        int c = hbase;
#pragma unroll
        for (int q = 0; q < 16; q++) {
            int h = s_hist[tid * 16 + q];
            if (c + h >= KSEL) { s_misc[1] = tid * 16 + q; s_misc[2] = c; break; }
            c += h;
        }
    }
    __syncthreads();

    bool useTop = (s_misc[0] >= KSEL);
    if (useTop) {
        int T = s_misc[1], n1 = s_misc[2];
        for (int q = 0; q < HW / 512; q++) {
            int i = tid * (HW / 512) + q;
            if (s_d2[i] < T) {
                int p = atomicAdd(&s_misc[3], 1);
                s_list[p] = ((unsigned long long)s_d2[i] << 32) | (unsigned)i;
            }
        }
        __syncthreads();
        if (tid >= n1 && tid < KSEL) s_list[tid] = ~0ULL;
        __syncthreads();
        for (int k = 2; k <= KSEL; k <<= 1)
            for (int j = k >> 1; j > 0; j >>= 1) {
                if (tid < KSEL) {
                    int ixj = tid ^ j;
                    if (ixj > tid) {
                        unsigned long long a = s_list[tid], c2 = s_list[ixj];
                        bool up = ((tid & k) == 0);
                        if ((a > c2) == up) { s_list[tid] = c2; s_list[ixj] = a; }
                    }
                }
                __syncthreads();
            }
        if (tid < n1) {
            int idx = (int)(s_list[tid] & 0xFFFFFFFFull);
            int match = (int)(keyF[b * HW + idx] & 0xFFFFFFFFull);
            out[outBase + tid * 2]     = (float)idx;
            out[outBase + tid * 2 + 1] = (float)match;
        }
        int myf[HW / 512], fsum = 0;
#pragma unroll
        for (int q = 0; q < HW / 512; q++) {
            int i = tid * (HW / 512) + q;
            myf[q] = (s_d2[i] == T);
            fsum += myf[q];
        }
        __syncthreads();
        s_part[tid] = fsum;
        __syncthreads();
        for (int off = 1; off < 512; off <<= 1) {
            int v = (tid >= off) ? s_part[tid - off] : 0;
            __syncthreads();
            s_part[tid] += v;
            __syncthreads();
        }
        int p = s_part[tid] - fsum;
        int need = KSEL - n1;
#pragma unroll
        for (int q = 0; q < HW / 512; q++) {
            if (myf[q]) {
                if (p < need) {
                    int i = tid * (HW / 512) + q;
                    int match = (int)(keyF[b * HW + i] & 0xFFFFFFFFull);
                    out[outBase + (n1 + p) * 2]     = (float)i;
                    out[outBase + (n1 + p) * 2 + 1] = (float)match;
                }
                p++;
            }
        }
    } else {
        if (tid < KSEL) {
            int idx = backup[b * KSEL + tid];
            int match = (int)(keyF[b * HW + idx] & 0xFFFFFFFFull);
            out[outBase + tid * 2]     = (float)idx;
            out[outBase + tid * 2 + 1] = (float)match;
        }
    }
}

// ---------------- launch ----------------------------------------------------
extern "C" void kernel_launch(void* const* d_in, const int* in_sizes, int n_in,
                              void* d_out, int out_size) {
    const float* f1 = nullptr; const float* f2 = nullptr;
    const int* mask1 = nullptr; const int* mask2 = nullptr;
    const int* bk1 = nullptr; const int* bk2 = nullptr;
    for (int i = 0; i < n_in; i++) {
        long long sz = in_sizes[i];
        if (sz == FEAT_N || sz == (long long)FEAT_N * 4) {
            if (!f1) f1 = (const float*)d_in[i]; else f2 = (const float*)d_in[i];
        } else if (sz == MASK_N || sz == (long long)MASK_N * 4) {
            if (!mask1) mask1 = (const int*)d_in[i]; else mask2 = (const int*)d_in[i];
        } else if (sz == BK_N || sz == (long long)BK_N * 4) {
            if (!bk1) bk1 = (const int*)d_in[i]; else bk2 = (const int*)d_in[i];
        }
    }
    if (!f1 || !f2 || !mask1 || !mask2 || !bk1 || !bk2) {
        f1    = (const float*)d_in[0];
        f2    = (const float*)d_in[1];
        mask1 = (const int*)d_in[2];
        mask2 = (const int*)d_in[3];
        bk1   = (const int*)d_in[4];
        bk2   = (const int*)d_in[5];
    }
    float* out = (float*)d_out;

    cudaFuncSetAttribute(mma_min_kernel,
                         cudaFuncAttributeMaxDynamicSharedMemorySize, SMEM_P1);

    normalize_kernel<<<2 * (MASK_N / 8), 256>>>(f1, f2, mask1, mask2);
    dim3 grid(HW / 128, HW / 128, BATCH);
    mma_min_kernel<<<grid, 256, SMEM_P1>>>(mask1, mask2);
    scan_kernel<<<2 * MASK_N / 8, 256>>>();
    refine_kernel<<<2048, 256>>>(f1, f2);
    topk_kernel<<<BATCH * 2, 512>>>(mask1, mask2, bk1, bk2, out);
}